// round 2
// baseline (speedup 1.0000x reference)
#include <cuda_runtime.h>
#include <math.h>

// Problem constants
#define NE 300000
#define NV 20000
#define NG 32
#define DD 128
#define HH 256

// ---------------- scratch (device globals; no allocation allowed) ----------
__device__ float g_e_pre[NE * DD];
__device__ float g_v_pre[NV * DD];
__device__ float g_u_pre[NG * DD];
__device__ float g_vA[NV * HH];
__device__ float g_vB[NV * HH];
__device__ float g_uD[NG * HH];
__device__ float g_h0[NE * HH];
__device__ float g_h1[NE * HH];
__device__ float g_enew[NE * DD];
__device__ float g_vesum[NV * DD];
__device__ int   g_vcnt[NV];
__device__ float g_uesum[NG * DD];
__device__ int   g_ecnt[NG];
__device__ float g_uvsum[NG * DD];
__device__ int   g_ncnt[NG];
__device__ float g_ncat[NV * 3 * DD];
__device__ float g_nh0[NV * HH];
__device__ float g_nh1[NV * HH];
__device__ float g_vnew[NV * DD];
__device__ float g_acat[NG * 3 * DD];
__device__ float g_ah0[NG * HH];
__device__ float g_ah1[NG * HH];
__device__ float g_unew[NG * DD];

__device__ __forceinline__ float sp(float x) {
    // jax.nn.softplus = max(x,0) + log1p(exp(-|x|))
    return fmaxf(x, 0.f) + log1pf(__expf(-fabsf(x)));
}

// ---------------------------------------------------------------------------
// Fused SGEMM: C[M,N] = epilogue(X[M,K] @ W[K,N])
// MODE 0: C = X@W (+bias if non-null), no activation
// MODE 1: C = softplus(X@W + bias)
// MODE 2: C = softplus(X@W + gb1[i1[r]] + gb2[i2[r]] + gb3[n2g[i1[r]]])
//         (edge layer-0: per-edge gathers of node/graph partial products;
//          the layer bias is folded into gb3)
// MODE 3: C = softplus(X@W + bias); out2 = C + skip  (final layer + residual)
//
// Tile 128x128x8, 256 threads, 8x8 per-thread microtile, double-buffered SMEM.
// Requires: K % 8 == 0, N % 128 == 0 (M arbitrary).
// ---------------------------------------------------------------------------
template <int MODE>
__global__ void __launch_bounds__(256, 2)
gemm_k(const float* __restrict__ X, const float* __restrict__ W,
       const float* __restrict__ bias, float* __restrict__ C,
       float* __restrict__ out2, const float* __restrict__ skip,
       const float* __restrict__ gb1, const float* __restrict__ gb2,
       const float* __restrict__ gb3,
       const int* __restrict__ i1, const int* __restrict__ i2,
       const int* __restrict__ n2g,
       int M, int K, int N)
{
    __shared__ float As[2][8][132];   // [buf][k][m], 132-pad: conflict-free
    __shared__ float Bs[2][8][128];   // [buf][k][n]

    const int tid  = threadIdx.x;
    const int row0 = blockIdx.y * 128;
    const int col0 = blockIdx.x * 128;
    const int tx = tid & 15, ty = tid >> 4;

    // X loader: each thread loads 4 consecutive K of one row, transposes
    const int lxm = tid >> 1;          // 0..127 (row within tile)
    const int lxk = (tid & 1) * 4;     // 0 or 4
    const int gr  = row0 + lxm;
    // W loader: each thread loads float4 along N of one k-row
    const int lwk = tid >> 5;          // 0..7
    const int lwn = (tid & 31) * 4;    // 0..124

    float acc[8][8];
#pragma unroll
    for (int i = 0; i < 8; i++)
#pragma unroll
        for (int j = 0; j < 8; j++) acc[i][j] = 0.f;

    const int ntiles = K >> 3;

    // prologue: tile 0 -> buf 0
    {
        float4 xv = make_float4(0.f, 0.f, 0.f, 0.f);
        if (gr < M) xv = *(const float4*)(X + (size_t)gr * K + lxk);
        As[0][lxk + 0][lxm] = xv.x;
        As[0][lxk + 1][lxm] = xv.y;
        As[0][lxk + 2][lxm] = xv.z;
        As[0][lxk + 3][lxm] = xv.w;
        float4 wv = *(const float4*)(W + (size_t)lwk * N + col0 + lwn);
        *(float4*)&Bs[0][lwk][lwn] = wv;
    }
    __syncthreads();

    for (int t = 0; t < ntiles; t++) {
        const int cur = t & 1;
        const bool has = (t + 1 < ntiles);
        float4 nxv = make_float4(0.f, 0.f, 0.f, 0.f);
        float4 nwv;
        if (has) {
            const int k0 = (t + 1) << 3;
            if (gr < M) nxv = *(const float4*)(X + (size_t)gr * K + k0 + lxk);
            nwv = *(const float4*)(W + (size_t)(k0 + lwk) * N + col0 + lwn);
        }

#pragma unroll
        for (int kk = 0; kk < 8; kk++) {
            float4 a0 = *(const float4*)&As[cur][kk][ty * 4];
            float4 a1 = *(const float4*)&As[cur][kk][64 + ty * 4];
            float4 b0 = *(const float4*)&Bs[cur][kk][tx * 4];
            float4 b1 = *(const float4*)&Bs[cur][kk][64 + tx * 4];
            float a[8] = {a0.x, a0.y, a0.z, a0.w, a1.x, a1.y, a1.z, a1.w};
            float b[8] = {b0.x, b0.y, b0.z, b0.w, b1.x, b1.y, b1.z, b1.w};
#pragma unroll
            for (int i = 0; i < 8; i++)
#pragma unroll
                for (int j = 0; j < 8; j++)
                    acc[i][j] = fmaf(a[i], b[j], acc[i][j]);
        }

        if (has) {
            const int nxt = cur ^ 1;
            As[nxt][lxk + 0][lxm] = nxv.x;
            As[nxt][lxk + 1][lxm] = nxv.y;
            As[nxt][lxk + 2][lxm] = nxv.z;
            As[nxt][lxk + 3][lxm] = nxv.w;
            *(float4*)&Bs[nxt][lwk][lwn] = nwv;
        }
        __syncthreads();
    }

    // ---------------- epilogue ----------------
    const int colb0 = col0 + tx * 4;
    const int colb1 = col0 + 64 + tx * 4;
    float4 bv0 = make_float4(0.f, 0.f, 0.f, 0.f), bv1 = bv0;
    if (MODE == 1 || MODE == 3 || (MODE == 0 && bias)) {
        bv0 = *(const float4*)(bias + colb0);
        bv1 = *(const float4*)(bias + colb1);
    }

#pragma unroll
    for (int h = 0; h < 2; h++) {
#pragma unroll
        for (int i = 0; i < 4; i++) {
            const int row = row0 + h * 64 + ty * 4 + i;
            if (row >= M) continue;
            const int r = h * 4 + i;

            float v[8];
            v[0] = acc[r][0] + bv0.x; v[1] = acc[r][1] + bv0.y;
            v[2] = acc[r][2] + bv0.z; v[3] = acc[r][3] + bv0.w;
            v[4] = acc[r][4] + bv1.x; v[5] = acc[r][5] + bv1.y;
            v[6] = acc[r][6] + bv1.z; v[7] = acc[r][7] + bv1.w;

            if (MODE == 2) {
                const int s = i1[row], d = i2[row], g = n2g[s];
                const float* p1 = gb1 + (size_t)s * N;
                const float* p2 = gb2 + (size_t)d * N;
                const float* p3 = gb3 + (size_t)g * N;
                float4 a10 = *(const float4*)(p1 + colb0);
                float4 a11 = *(const float4*)(p1 + colb1);
                float4 a20 = *(const float4*)(p2 + colb0);
                float4 a21 = *(const float4*)(p2 + colb1);
                float4 a30 = *(const float4*)(p3 + colb0);
                float4 a31 = *(const float4*)(p3 + colb1);
                v[0] += a10.x + a20.x + a30.x; v[1] += a10.y + a20.y + a30.y;
                v[2] += a10.z + a20.z + a30.z; v[3] += a10.w + a20.w + a30.w;
                v[4] += a11.x + a21.x + a31.x; v[5] += a11.y + a21.y + a31.y;
                v[6] += a11.z + a21.z + a31.z; v[7] += a11.w + a21.w + a31.w;
            }
            if (MODE != 0) {
#pragma unroll
                for (int j = 0; j < 8; j++) v[j] = sp(v[j]);
            }
            float4 o0 = make_float4(v[0], v[1], v[2], v[3]);
            float4 o1 = make_float4(v[4], v[5], v[6], v[7]);
            *(float4*)(C + (size_t)row * N + colb0) = o0;
            *(float4*)(C + (size_t)row * N + colb1) = o1;
            if (MODE == 3) {
                float4 s0 = *(const float4*)(skip + (size_t)row * N + colb0);
                float4 s1 = *(const float4*)(skip + (size_t)row * N + colb1);
                o0.x += s0.x; o0.y += s0.y; o0.z += s0.z; o0.w += s0.w;
                o1.x += s1.x; o1.y += s1.y; o1.z += s1.z; o1.w += s1.w;
                *(float4*)(out2 + (size_t)row * N + colb0) = o0;
                *(float4*)(out2 + (size_t)row * N + colb1) = o1;
            }
        }
    }
}

// ---------------- segment-count kernel -------------------------------------
__global__ void counts_k(const int* __restrict__ src, const int* __restrict__ dst,
                         const int* __restrict__ n2g)
{
    int i = blockIdx.x * blockDim.x + threadIdx.x;
    if (i < NE) {
        atomicAdd(&g_vcnt[dst[i]], 1);
        atomicAdd(&g_ecnt[n2g[src[i]]], 1);
    }
    if (i < NV) atomicAdd(&g_ncnt[n2g[i]], 1);
}

// ---------------- edge segment sums: ve_sum (by dst), ue_sum (by graph) ----
__global__ void edge_seg_k(const int* __restrict__ src, const int* __restrict__ dst,
                           const int* __restrict__ n2g)
{
    __shared__ float s_ue[NG * DD];
    for (int i = threadIdx.x; i < NG * DD; i += blockDim.x) s_ue[i] = 0.f;
    __syncthreads();

    const int total = NE * (DD / 4);
    for (int idx = blockIdx.x * blockDim.x + threadIdx.x; idx < total;
         idx += gridDim.x * blockDim.x) {
        int e = idx >> 5;
        int c = (idx & 31) * 4;
        float4 v = *(const float4*)(g_enew + (size_t)e * DD + c);
        int dn = dst[e];
        int g  = n2g[src[e]];
        float* vp = g_vesum + (size_t)dn * DD + c;
        atomicAdd(vp + 0, v.x); atomicAdd(vp + 1, v.y);
        atomicAdd(vp + 2, v.z); atomicAdd(vp + 3, v.w);
        float* up = s_ue + g * DD + c;
        atomicAdd(up + 0, v.x); atomicAdd(up + 1, v.y);
        atomicAdd(up + 2, v.z); atomicAdd(up + 3, v.w);
    }
    __syncthreads();
    for (int i = threadIdx.x; i < NG * DD; i += blockDim.x) {
        float v = s_ue[i];
        if (v != 0.f) atomicAdd(&g_uesum[i], v);
    }
}

// ---------------- node segment sums: uv_sum (by graph) ---------------------
__global__ void node_seg_k(const int* __restrict__ n2g)
{
    __shared__ float s_uv[NG * DD];
    for (int i = threadIdx.x; i < NG * DD; i += blockDim.x) s_uv[i] = 0.f;
    __syncthreads();

    const int total = NV * (DD / 4);
    for (int idx = blockIdx.x * blockDim.x + threadIdx.x; idx < total;
         idx += gridDim.x * blockDim.x) {
        int node = idx >> 5;
        int c = (idx & 31) * 4;
        float4 v = *(const float4*)(g_vnew + (size_t)node * DD + c);
        int g = n2g[node];
        float* up = s_uv + g * DD + c;
        atomicAdd(up + 0, v.x); atomicAdd(up + 1, v.y);
        atomicAdd(up + 2, v.z); atomicAdd(up + 3, v.w);
    }
    __syncthreads();
    for (int i = threadIdx.x; i < NG * DD; i += blockDim.x) {
        float v = s_uv[i];
        if (v != 0.f) atomicAdd(&g_uvsum[i], v);
    }
}

// ---------------- node concat: [v_pre | ve_mean | u_pre[g]] ---------------
__global__ void nodecat_k(const int* __restrict__ n2g)
{
    int idx = blockIdx.x * blockDim.x + threadIdx.x;
    const int total = NV * (DD / 4);
    if (idx >= total) return;
    int node = idx >> 5;
    int c = (idx & 31) * 4;

    float4 vp = *(const float4*)(g_v_pre + (size_t)node * DD + c);
    *(float4*)(g_ncat + (size_t)node * 384 + c) = vp;

    float cnt = fmaxf((float)g_vcnt[node], 1.f);
    float4 ve = *(const float4*)(g_vesum + (size_t)node * DD + c);
    ve.x /= cnt; ve.y /= cnt; ve.z /= cnt; ve.w /= cnt;
    *(float4*)(g_ncat + (size_t)node * 384 + 128 + c) = ve;

    int g = n2g[node];
    float4 up = *(const float4*)(g_u_pre + (size_t)g * DD + c);
    *(float4*)(g_ncat + (size_t)node * 384 + 256 + c) = up;
}

// ---------------- attr concat: [u_pre | ue_mean | uv_mean] -----------------
__global__ void attrcat_k()
{
    int idx = blockIdx.x * blockDim.x + threadIdx.x;
    if (idx >= NG * (DD / 4)) return;
    int g = idx >> 5;
    int c = (idx & 31) * 4;

    float4 u = *(const float4*)(g_u_pre + (size_t)g * DD + c);
    *(float4*)(g_acat + (size_t)g * 384 + c) = u;

    float ec = fmaxf((float)g_ecnt[g], 1.f);
    float4 ue = *(const float4*)(g_uesum + (size_t)g * DD + c);
    ue.x /= ec; ue.y /= ec; ue.z /= ec; ue.w /= ec;
    *(float4*)(g_acat + (size_t)g * 384 + 128 + c) = ue;

    float nc = fmaxf((float)g_ncnt[g], 1.f);
    float4 uv = *(const float4*)(g_uvsum + (size_t)g * DD + c);
    uv.x /= nc; uv.y /= nc; uv.z /= nc; uv.w /= nc;
    *(float4*)(g_acat + (size_t)g * 384 + 256 + c) = uv;
}

// ---------------------------------------------------------------------------
extern "C" void kernel_launch(void* const* d_in, const int* in_sizes, int n_in,
                              void* d_out, int out_size)
{
    const float* edge_feat  = (const float*)d_in[0];
    const float* node_feat  = (const float*)d_in[1];
    const float* graph_attr = (const float*)d_in[2];
    const int*   src        = (const int*)d_in[3];
    const int*   dst        = (const int*)d_in[4];
    const int*   n2g        = (const int*)d_in[5];
    const float* peW = (const float*)d_in[6],  *peb = (const float*)d_in[7];
    const float* pnW = (const float*)d_in[8],  *pnb = (const float*)d_in[9];
    const float* paW = (const float*)d_in[10], *pab = (const float*)d_in[11];
    const float* eW0 = (const float*)d_in[12], *eb0 = (const float*)d_in[13];
    const float* eW1 = (const float*)d_in[14], *eb1 = (const float*)d_in[15];
    const float* eW2 = (const float*)d_in[16], *eb2 = (const float*)d_in[17];
    const float* nW0 = (const float*)d_in[18], *nb0 = (const float*)d_in[19];
    const float* nW1 = (const float*)d_in[20], *nb1 = (const float*)d_in[21];
    const float* nW2 = (const float*)d_in[22], *nb2 = (const float*)d_in[23];
    const float* aW0 = (const float*)d_in[24], *ab0 = (const float*)d_in[25];
    const float* aW1 = (const float*)d_in[26], *ab1 = (const float*)d_in[27];
    const float* aW2 = (const float*)d_in[28], *ab2 = (const float*)d_in[29];
    float* out = (float*)d_out;

    float *e_pre, *v_pre, *u_pre, *vA, *vB, *uD, *h0, *h1, *enew;
    float *vesum, *uesum, *uvsum, *ncat, *nh0, *nh1, *vnew, *acat, *ah0, *ah1, *unew;
    int *vcnt, *ecnt, *ncnt;
    cudaGetSymbolAddress((void**)&e_pre, g_e_pre);
    cudaGetSymbolAddress((void**)&v_pre, g_v_pre);
    cudaGetSymbolAddress((void**)&u_pre, g_u_pre);
    cudaGetSymbolAddress((void**)&vA,    g_vA);
    cudaGetSymbolAddress((void**)&vB,    g_vB);
    cudaGetSymbolAddress((void**)&uD,    g_uD);
    cudaGetSymbolAddress((void**)&h0,    g_h0);
    cudaGetSymbolAddress((void**)&h1,    g_h1);
    cudaGetSymbolAddress((void**)&enew,  g_enew);
    cudaGetSymbolAddress((void**)&vesum, g_vesum);
    cudaGetSymbolAddress((void**)&uesum, g_uesum);
    cudaGetSymbolAddress((void**)&uvsum, g_uvsum);
    cudaGetSymbolAddress((void**)&ncat,  g_ncat);
    cudaGetSymbolAddress((void**)&nh0,   g_nh0);
    cudaGetSymbolAddress((void**)&nh1,   g_nh1);
    cudaGetSymbolAddress((void**)&vnew,  g_vnew);
    cudaGetSymbolAddress((void**)&acat,  g_acat);
    cudaGetSymbolAddress((void**)&ah0,   g_ah0);
    cudaGetSymbolAddress((void**)&ah1,   g_ah1);
    cudaGetSymbolAddress((void**)&unew,  g_unew);
    cudaGetSymbolAddress((void**)&vcnt,  g_vcnt);
    cudaGetSymbolAddress((void**)&ecnt,  g_ecnt);
    cudaGetSymbolAddress((void**)&ncnt,  g_ncnt);

    // zero the accumulators (graph-capturable memset nodes)
    cudaMemsetAsync(vesum, 0, sizeof(float) * NV * DD, 0);
    cudaMemsetAsync(vcnt,  0, sizeof(int) * NV, 0);
    cudaMemsetAsync(uesum, 0, sizeof(float) * NG * DD, 0);
    cudaMemsetAsync(ecnt,  0, sizeof(int) * NG, 0);
    cudaMemsetAsync(uvsum, 0, sizeof(float) * NG * DD, 0);
    cudaMemsetAsync(ncnt,  0, sizeof(int) * NG, 0);

    auto grd = [](int M, int N) {
        return dim3((unsigned)(N / 128), (unsigned)((M + 127) / 128));
    };
#define NUL nullptr, nullptr, nullptr, nullptr, nullptr, nullptr, nullptr, nullptr

    // pre-dense MLPs
    gemm_k<1><<<grd(NE, DD), 256>>>(edge_feat,  peW, peb, e_pre, NUL, NE, DD, DD);
    gemm_k<1><<<grd(NV, DD), 256>>>(node_feat,  pnW, pnb, v_pre, NUL, NV, DD, DD);
    gemm_k<1><<<grd(NG, DD), 256>>>(graph_attr, paW, pab, u_pre, NUL, NG, DD, DD);

    // per-node / per-graph partial products of edge layer 0 (K-panel split)
    gemm_k<0><<<grd(NV, HH), 256>>>(v_pre, eW0,             nullptr, vA, NUL, NV, DD, HH);
    gemm_k<0><<<grd(NV, HH), 256>>>(v_pre, eW0 + 128 * HH,  nullptr, vB, NUL, NV, DD, HH);
    gemm_k<0><<<grd(NG, HH), 256>>>(u_pre, eW0 + 384 * HH,  eb0,     uD, NUL, NG, DD, HH);

    counts_k<<<(NE + 255) / 256, 256>>>(src, dst, n2g);

    // edge MLP
    gemm_k<2><<<grd(NE, HH), 256>>>(e_pre, eW0 + 256 * HH, nullptr, h0,
                                    nullptr, nullptr, vA, vB, uD, src, dst, n2g,
                                    NE, DD, HH);
    gemm_k<1><<<grd(NE, HH), 256>>>(h0, eW1, eb1, h1, NUL, NE, HH, HH);
    gemm_k<3><<<grd(NE, DD), 256>>>(h1, eW2, eb2, enew, out, edge_feat,
                                    nullptr, nullptr, nullptr, nullptr, nullptr, nullptr,
                                    NE, HH, DD);

    // segment means of e_new
    edge_seg_k<<<512, 256>>>(src, dst, n2g);

    // node MLP
    nodecat_k<<<(NV * 32 + 255) / 256, 256>>>(n2g);
    gemm_k<1><<<grd(NV, HH), 256>>>(ncat, nW0, nb0, nh0, NUL, NV, 384, HH);
    gemm_k<1><<<grd(NV, HH), 256>>>(nh0, nW1, nb1, nh1, NUL, NV, HH, HH);
    gemm_k<3><<<grd(NV, DD), 256>>>(nh1, nW2, nb2, vnew, out + (size_t)NE * DD, node_feat,
                                    nullptr, nullptr, nullptr, nullptr, nullptr, nullptr,
                                    NV, HH, DD);

    // graph readout of v_new
    node_seg_k<<<256, 256>>>(n2g);

    // attr MLP
    attrcat_k<<<4, 256>>>();
    gemm_k<1><<<grd(NG, HH), 256>>>(acat, aW0, ab0, ah0, NUL, NG, 384, HH);
    gemm_k<1><<<grd(NG, HH), 256>>>(ah0, aW1, ab1, ah1, NUL, NG, HH, HH);
    gemm_k<3><<<grd(NG, DD), 256>>>(ah1, aW2, ab2, unew,
                                    out + (size_t)NE * DD + (size_t)NV * DD, graph_attr,
                                    nullptr, nullptr, nullptr, nullptr, nullptr, nullptr,
                                    NG, HH, DD);
#undef NUL
}

// round 3
// speedup vs baseline: 1.0092x; 1.0092x over previous
#include <cuda_runtime.h>
#include <math.h>

// Problem constants
#define NE 300000
#define NV 20000
#define NG 32
#define DD 128
#define HH 256

// ---------------- scratch (device globals; no allocation allowed) ----------
__device__ float g_e_pre[NE * DD];
__device__ float g_v_pre[NV * DD];
__device__ float g_u_pre[NG * DD];
__device__ float g_vA[NV * HH];
__device__ float g_vB[NV * HH];
__device__ float g_uD[NG * HH];
__device__ float g_h0[NE * HH];
__device__ float g_h1[NE * HH];
__device__ float g_enew[NE * DD];
__device__ float g_vesum[NV * DD];
__device__ int   g_vcnt[NV];
__device__ float g_uesum[NG * DD];
__device__ int   g_ecnt[NG];
__device__ float g_uvsum[NG * DD];
__device__ int   g_ncnt[NG];
__device__ float g_ncat[NV * 3 * DD];
__device__ float g_nh0[NV * HH];
__device__ float g_nh1[NV * HH];
__device__ float g_vnew[NV * DD];
__device__ float g_acat[NG * 3 * DD];
__device__ float g_ah0[NG * HH];
__device__ float g_ah1[NG * HH];
__device__ float g_unew[NG * DD];

__device__ __forceinline__ float sp(float x) {
    // jax.nn.softplus = max(x,0) + log1p(exp(-|x|))
    return fmaxf(x, 0.f) + log1pf(__expf(-fabsf(x)));
}

// packed f32x2 helpers (sm_100+)
#define FMA2(d, a, b) \
    asm("fma.rn.f32x2 %0, %1, %2, %0;" : "+l"(d) : "l"(a), "l"(b))
#define PACK2(d, lo, hi) \
    asm("mov.b64 %0, {%1, %2};" : "=l"(d) : "r"(__float_as_uint(lo)), "r"(__float_as_uint(hi)))
#define UNPACK2(lo, hi, s) \
    do { unsigned int _ulo, _uhi; \
         asm("mov.b64 {%0, %1}, %2;" : "=r"(_ulo), "=r"(_uhi) : "l"(s)); \
         lo = __uint_as_float(_ulo); hi = __uint_as_float(_uhi); } while (0)

// ---------------------------------------------------------------------------
// Fused SGEMM: C[M,N] = epilogue(X[M,K] @ W[K,N])
// MODE 0: C = X@W (+bias if non-null), no activation
// MODE 1: C = softplus(X@W + bias)
// MODE 2: C = softplus(X@W + gb1[i1[r]] + gb2[i2[r]] + gb3[n2g[i1[r]]])
//         (edge layer-0: per-edge gathers of node/graph partial products;
//          the layer bias is folded into gb3)
// MODE 3: C = softplus(X@W + bias); out2 = C + skip  (final layer + residual)
//
// Tile 128x128x8, 256 threads, 8x8 per-thread microtile computed as 8x4
// f32x2 pairs (fma.rn.f32x2 = 2 FMA/issue), double-buffered SMEM.
// Requires: K % 8 == 0, N % 128 == 0 (M arbitrary).
// ---------------------------------------------------------------------------
template <int MODE>
__global__ void __launch_bounds__(256, 2)
gemm_k(const float* __restrict__ X, const float* __restrict__ W,
       const float* __restrict__ bias, float* __restrict__ C,
       float* __restrict__ out2, const float* __restrict__ skip,
       const float* __restrict__ gb1, const float* __restrict__ gb2,
       const float* __restrict__ gb3,
       const int* __restrict__ i1, const int* __restrict__ i2,
       const int* __restrict__ n2g,
       int M, int K, int N)
{
    __shared__ float As[2][8][132];   // [buf][k][m], 132-pad: conflict-free
    __shared__ float Bs[2][8][128];   // [buf][k][n]

    const int tid  = threadIdx.x;
    const int row0 = blockIdx.y * 128;
    const int col0 = blockIdx.x * 128;
    const int tx = tid & 15, ty = tid >> 4;

    // X loader: each thread loads 4 consecutive K of one row, transposes
    const int lxm = tid >> 1;          // 0..127 (row within tile)
    const int lxk = (tid & 1) * 4;     // 0 or 4
    const int gr  = row0 + lxm;
    // W loader: each thread loads float4 along N of one k-row
    const int lwk = tid >> 5;          // 0..7
    const int lwn = (tid & 31) * 4;    // 0..124

    // 8 rows x 4 column-pairs of packed f32x2 accumulators
    unsigned long long acc2[8][4];
#pragma unroll
    for (int i = 0; i < 8; i++)
#pragma unroll
        for (int j = 0; j < 4; j++) acc2[i][j] = 0ULL;

    const int ntiles = K >> 3;

    // prologue: tile 0 -> buf 0
    {
        float4 xv = make_float4(0.f, 0.f, 0.f, 0.f);
        if (gr < M) xv = *(const float4*)(X + (size_t)gr * K + lxk);
        As[0][lxk + 0][lxm] = xv.x;
        As[0][lxk + 1][lxm] = xv.y;
        As[0][lxk + 2][lxm] = xv.z;
        As[0][lxk + 3][lxm] = xv.w;
        float4 wv = *(const float4*)(W + (size_t)lwk * N + col0 + lwn);
        *(float4*)&Bs[0][lwk][lwn] = wv;
    }
    __syncthreads();

    for (int t = 0; t < ntiles; t++) {
        const int cur = t & 1;
        const bool has = (t + 1 < ntiles);
        float4 nxv = make_float4(0.f, 0.f, 0.f, 0.f);
        float4 nwv;
        if (has) {
            const int k0 = (t + 1) << 3;
            if (gr < M) nxv = *(const float4*)(X + (size_t)gr * K + k0 + lxk);
            nwv = *(const float4*)(W + (size_t)(k0 + lwk) * N + col0 + lwn);
        }

#pragma unroll
        for (int kk = 0; kk < 8; kk++) {
            float4 a0 = *(const float4*)&As[cur][kk][ty * 4];
            float4 a1 = *(const float4*)&As[cur][kk][64 + ty * 4];
            float4 b0 = *(const float4*)&Bs[cur][kk][tx * 4];
            float4 b1 = *(const float4*)&Bs[cur][kk][64 + tx * 4];

            unsigned long long bb0, bb1, bb2, bb3;
            PACK2(bb0, b0.x, b0.y);
            PACK2(bb1, b0.z, b0.w);
            PACK2(bb2, b1.x, b1.y);
            PACK2(bb3, b1.z, b1.w);

            float a[8] = {a0.x, a0.y, a0.z, a0.w, a1.x, a1.y, a1.z, a1.w};
#pragma unroll
            for (int i = 0; i < 8; i++) {
                unsigned long long aa;
                PACK2(aa, a[i], a[i]);
                FMA2(acc2[i][0], aa, bb0);
                FMA2(acc2[i][1], aa, bb1);
                FMA2(acc2[i][2], aa, bb2);
                FMA2(acc2[i][3], aa, bb3);
            }
        }

        if (has) {
            const int nxt = cur ^ 1;
            As[nxt][lxk + 0][lxm] = nxv.x;
            As[nxt][lxk + 1][lxm] = nxv.y;
            As[nxt][lxk + 2][lxm] = nxv.z;
            As[nxt][lxk + 3][lxm] = nxv.w;
            *(float4*)&Bs[nxt][lwk][lwn] = nwv;
        }
        __syncthreads();
    }

    // ---------------- epilogue ----------------
    const int colb0 = col0 + tx * 4;
    const int colb1 = col0 + 64 + tx * 4;
    float4 bv0 = make_float4(0.f, 0.f, 0.f, 0.f), bv1 = bv0;
    if (MODE == 1 || MODE == 3 || (MODE == 0 && bias)) {
        bv0 = *(const float4*)(bias + colb0);
        bv1 = *(const float4*)(bias + colb1);
    }

#pragma unroll
    for (int h = 0; h < 2; h++) {
#pragma unroll
        for (int i = 0; i < 4; i++) {
            const int row = row0 + h * 64 + ty * 4 + i;
            if (row >= M) continue;
            const int r = h * 4 + i;

            float v[8];
            UNPACK2(v[0], v[1], acc2[r][0]);
            UNPACK2(v[2], v[3], acc2[r][1]);
            UNPACK2(v[4], v[5], acc2[r][2]);
            UNPACK2(v[6], v[7], acc2[r][3]);
            v[0] += bv0.x; v[1] += bv0.y; v[2] += bv0.z; v[3] += bv0.w;
            v[4] += bv1.x; v[5] += bv1.y; v[6] += bv1.z; v[7] += bv1.w;

            if (MODE == 2) {
                const int s = i1[row], d = i2[row], g = n2g[s];
                const float* p1 = gb1 + (size_t)s * N;
                const float* p2 = gb2 + (size_t)d * N;
                const float* p3 = gb3 + (size_t)g * N;
                float4 a10 = *(const float4*)(p1 + colb0);
                float4 a11 = *(const float4*)(p1 + colb1);
                float4 a20 = *(const float4*)(p2 + colb0);
                float4 a21 = *(const float4*)(p2 + colb1);
                float4 a30 = *(const float4*)(p3 + colb0);
                float4 a31 = *(const float4*)(p3 + colb1);
                v[0] += a10.x + a20.x + a30.x; v[1] += a10.y + a20.y + a30.y;
                v[2] += a10.z + a20.z + a30.z; v[3] += a10.w + a20.w + a30.w;
                v[4] += a11.x + a21.x + a31.x; v[5] += a11.y + a21.y + a31.y;
                v[6] += a11.z + a21.z + a31.z; v[7] += a11.w + a21.w + a31.w;
            }
            if (MODE != 0) {
#pragma unroll
                for (int j = 0; j < 8; j++) v[j] = sp(v[j]);
            }
            float4 o0 = make_float4(v[0], v[1], v[2], v[3]);
            float4 o1 = make_float4(v[4], v[5], v[6], v[7]);
            *(float4*)(C + (size_t)row * N + colb0) = o0;
            *(float4*)(C + (size_t)row * N + colb1) = o1;
            if (MODE == 3) {
                float4 s0 = *(const float4*)(skip + (size_t)row * N + colb0);
                float4 s1 = *(const float4*)(skip + (size_t)row * N + colb1);
                o0.x += s0.x; o0.y += s0.y; o0.z += s0.z; o0.w += s0.w;
                o1.x += s1.x; o1.y += s1.y; o1.z += s1.z; o1.w += s1.w;
                *(float4*)(out2 + (size_t)row * N + colb0) = o0;
                *(float4*)(out2 + (size_t)row * N + colb1) = o1;
            }
        }
    }
}

// ---------------- segment-count kernel -------------------------------------
__global__ void counts_k(const int* __restrict__ src, const int* __restrict__ dst,
                         const int* __restrict__ n2g)
{
    int i = blockIdx.x * blockDim.x + threadIdx.x;
    if (i < NE) {
        atomicAdd(&g_vcnt[dst[i]], 1);
        atomicAdd(&g_ecnt[n2g[src[i]]], 1);
    }
    if (i < NV) atomicAdd(&g_ncnt[n2g[i]], 1);
}

// ---------------- edge segment sums: ve_sum (by dst), ue_sum (by graph) ----
__global__ void edge_seg_k(const int* __restrict__ src, const int* __restrict__ dst,
                           const int* __restrict__ n2g)
{
    __shared__ float s_ue[NG * DD];
    for (int i = threadIdx.x; i < NG * DD; i += blockDim.x) s_ue[i] = 0.f;
    __syncthreads();

    const int total = NE * (DD / 4);
    for (int idx = blockIdx.x * blockDim.x + threadIdx.x; idx < total;
         idx += gridDim.x * blockDim.x) {
        int e = idx >> 5;
        int c = (idx & 31) * 4;
        float4 v = *(const float4*)(g_enew + (size_t)e * DD + c);
        int dn = dst[e];
        int g  = n2g[src[e]];
        float* vp = g_vesum + (size_t)dn * DD + c;
        atomicAdd(vp + 0, v.x); atomicAdd(vp + 1, v.y);
        atomicAdd(vp + 2, v.z); atomicAdd(vp + 3, v.w);
        float* up = s_ue + g * DD + c;
        atomicAdd(up + 0, v.x); atomicAdd(up + 1, v.y);
        atomicAdd(up + 2, v.z); atomicAdd(up + 3, v.w);
    }
    __syncthreads();
    for (int i = threadIdx.x; i < NG * DD; i += blockDim.x) {
        float v = s_ue[i];
        if (v != 0.f) atomicAdd(&g_uesum[i], v);
    }
}

// ---------------- node segment sums: uv_sum (by graph) ---------------------
__global__ void node_seg_k(const int* __restrict__ n2g)
{
    __shared__ float s_uv[NG * DD];
    for (int i = threadIdx.x; i < NG * DD; i += blockDim.x) s_uv[i] = 0.f;
    __syncthreads();

    const int total = NV * (DD / 4);
    for (int idx = blockIdx.x * blockDim.x + threadIdx.x; idx < total;
         idx += gridDim.x * blockDim.x) {
        int node = idx >> 5;
        int c = (idx & 31) * 4;
        float4 v = *(const float4*)(g_vnew + (size_t)node * DD + c);
        int g = n2g[node];
        float* up = s_uv + g * DD + c;
        atomicAdd(up + 0, v.x); atomicAdd(up + 1, v.y);
        atomicAdd(up + 2, v.z); atomicAdd(up + 3, v.w);
    }
    __syncthreads();
    for (int i = threadIdx.x; i < NG * DD; i += blockDim.x) {
        float v = s_uv[i];
        if (v != 0.f) atomicAdd(&g_uvsum[i], v);
    }
}

// ---------------- node concat: [v_pre | ve_mean | u_pre[g]] ---------------
__global__ void nodecat_k(const int* __restrict__ n2g)
{
    int idx = blockIdx.x * blockDim.x + threadIdx.x;
    const int total = NV * (DD / 4);
    if (idx >= total) return;
    int node = idx >> 5;
    int c = (idx & 31) * 4;

    float4 vp = *(const float4*)(g_v_pre + (size_t)node * DD + c);
    *(float4*)(g_ncat + (size_t)node * 384 + c) = vp;

    float cnt = fmaxf((float)g_vcnt[node], 1.f);
    float4 ve = *(const float4*)(g_vesum + (size_t)node * DD + c);
    ve.x /= cnt; ve.y /= cnt; ve.z /= cnt; ve.w /= cnt;
    *(float4*)(g_ncat + (size_t)node * 384 + 128 + c) = ve;

    int g = n2g[node];
    float4 up = *(const float4*)(g_u_pre + (size_t)g * DD + c);
    *(float4*)(g_ncat + (size_t)node * 384 + 256 + c) = up;
}

// ---------------- attr concat: [u_pre | ue_mean | uv_mean] -----------------
__global__ void attrcat_k()
{
    int idx = blockIdx.x * blockDim.x + threadIdx.x;
    if (idx >= NG * (DD / 4)) return;
    int g = idx >> 5;
    int c = (idx & 31) * 4;

    float4 u = *(const float4*)(g_u_pre + (size_t)g * DD + c);
    *(float4*)(g_acat + (size_t)g * 384 + c) = u;

    float ec = fmaxf((float)g_ecnt[g], 1.f);
    float4 ue = *(const float4*)(g_uesum + (size_t)g * DD + c);
    ue.x /= ec; ue.y /= ec; ue.z /= ec; ue.w /= ec;
    *(float4*)(g_acat + (size_t)g * 384 + 128 + c) = ue;

    float nc = fmaxf((float)g_ncnt[g], 1.f);
    float4 uv = *(const float4*)(g_uvsum + (size_t)g * DD + c);
    uv.x /= nc; uv.y /= nc; uv.z /= nc; uv.w /= nc;
    *(float4*)(g_acat + (size_t)g * 384 + 256 + c) = uv;
}

// ---------------------------------------------------------------------------
extern "C" void kernel_launch(void* const* d_in, const int* in_sizes, int n_in,
                              void* d_out, int out_size)
{
    const float* edge_feat  = (const float*)d_in[0];
    const float* node_feat  = (const float*)d_in[1];
    const float* graph_attr = (const float*)d_in[2];
    const int*   src        = (const int*)d_in[3];
    const int*   dst        = (const int*)d_in[4];
    const int*   n2g        = (const int*)d_in[5];
    const float* peW = (const float*)d_in[6],  *peb = (const float*)d_in[7];
    const float* pnW = (const float*)d_in[8],  *pnb = (const float*)d_in[9];
    const float* paW = (const float*)d_in[10], *pab = (const float*)d_in[11];
    const float* eW0 = (const float*)d_in[12], *eb0 = (const float*)d_in[13];
    const float* eW1 = (const float*)d_in[14], *eb1 = (const float*)d_in[15];
    const float* eW2 = (const float*)d_in[16], *eb2 = (const float*)d_in[17];
    const float* nW0 = (const float*)d_in[18], *nb0 = (const float*)d_in[19];
    const float* nW1 = (const float*)d_in[20], *nb1 = (const float*)d_in[21];
    const float* nW2 = (const float*)d_in[22], *nb2 = (const float*)d_in[23];
    const float* aW0 = (const float*)d_in[24], *ab0 = (const float*)d_in[25];
    const float* aW1 = (const float*)d_in[26], *ab1 = (const float*)d_in[27];
    const float* aW2 = (const float*)d_in[28], *ab2 = (const float*)d_in[29];
    float* out = (float*)d_out;

    float *e_pre, *v_pre, *u_pre, *vA, *vB, *uD, *h0, *h1, *enew;
    float *vesum, *uesum, *uvsum, *ncat, *nh0, *nh1, *vnew, *acat, *ah0, *ah1, *unew;
    int *vcnt, *ecnt, *ncnt;
    cudaGetSymbolAddress((void**)&e_pre, g_e_pre);
    cudaGetSymbolAddress((void**)&v_pre, g_v_pre);
    cudaGetSymbolAddress((void**)&u_pre, g_u_pre);
    cudaGetSymbolAddress((void**)&vA,    g_vA);
    cudaGetSymbolAddress((void**)&vB,    g_vB);
    cudaGetSymbolAddress((void**)&uD,    g_uD);
    cudaGetSymbolAddress((void**)&h0,    g_h0);
    cudaGetSymbolAddress((void**)&h1,    g_h1);
    cudaGetSymbolAddress((void**)&enew,  g_enew);
    cudaGetSymbolAddress((void**)&vesum, g_vesum);
    cudaGetSymbolAddress((void**)&uesum, g_uesum);
    cudaGetSymbolAddress((void**)&uvsum, g_uvsum);
    cudaGetSymbolAddress((void**)&ncat,  g_ncat);
    cudaGetSymbolAddress((void**)&nh0,   g_nh0);
    cudaGetSymbolAddress((void**)&nh1,   g_nh1);
    cudaGetSymbolAddress((void**)&vnew,  g_vnew);
    cudaGetSymbolAddress((void**)&acat,  g_acat);
    cudaGetSymbolAddress((void**)&ah0,   g_ah0);
    cudaGetSymbolAddress((void**)&ah1,   g_ah1);
    cudaGetSymbolAddress((void**)&unew,  g_unew);
    cudaGetSymbolAddress((void**)&vcnt,  g_vcnt);
    cudaGetSymbolAddress((void**)&ecnt,  g_ecnt);
    cudaGetSymbolAddress((void**)&ncnt,  g_ncnt);

    // zero the accumulators (graph-capturable memset nodes)
    cudaMemsetAsync(vesum, 0, sizeof(float) * NV * DD, 0);
    cudaMemsetAsync(vcnt,  0, sizeof(int) * NV, 0);
    cudaMemsetAsync(uesum, 0, sizeof(float) * NG * DD, 0);
    cudaMemsetAsync(ecnt,  0, sizeof(int) * NG, 0);
    cudaMemsetAsync(uvsum, 0, sizeof(float) * NG * DD, 0);
    cudaMemsetAsync(ncnt,  0, sizeof(int) * NG, 0);

    auto grd = [](int M, int N) {
        return dim3((unsigned)(N / 128), (unsigned)((M + 127) / 128));
    };
#define NUL nullptr, nullptr, nullptr, nullptr, nullptr, nullptr, nullptr, nullptr

    // pre-dense MLPs
    gemm_k<1><<<grd(NE, DD), 256>>>(edge_feat,  peW, peb, e_pre, NUL, NE, DD, DD);
    gemm_k<1><<<grd(NV, DD), 256>>>(node_feat,  pnW, pnb, v_pre, NUL, NV, DD, DD);
    gemm_k<1><<<grd(NG, DD), 256>>>(graph_attr, paW, pab, u_pre, NUL, NG, DD, DD);

    // per-node / per-graph partial products of edge layer 0 (K-panel split)
    gemm_k<0><<<grd(NV, HH), 256>>>(v_pre, eW0,             nullptr, vA, NUL, NV, DD, HH);
    gemm_k<0><<<grd(NV, HH), 256>>>(v_pre, eW0 + 128 * HH,  nullptr, vB, NUL, NV, DD, HH);
    gemm_k<0><<<grd(NG, HH), 256>>>(u_pre, eW0 + 384 * HH,  eb0,     uD, NUL, NG, DD, HH);

    counts_k<<<(NE + 255) / 256, 256>>>(src, dst, n2g);

    // edge MLP
    gemm_k<2><<<grd(NE, HH), 256>>>(e_pre, eW0 + 256 * HH, nullptr, h0,
                                    nullptr, nullptr, vA, vB, uD, src, dst, n2g,
                                    NE, DD, HH);
    gemm_k<1><<<grd(NE, HH), 256>>>(h0, eW1, eb1, h1, NUL, NE, HH, HH);
    gemm_k<3><<<grd(NE, DD), 256>>>(h1, eW2, eb2, enew, out, edge_feat,
                                    nullptr, nullptr, nullptr, nullptr, nullptr, nullptr,
                                    NE, HH, DD);

    // segment means of e_new
    edge_seg_k<<<512, 256>>>(src, dst, n2g);

    // node MLP
    nodecat_k<<<(NV * 32 + 255) / 256, 256>>>(n2g);
    gemm_k<1><<<grd(NV, HH), 256>>>(ncat, nW0, nb0, nh0, NUL, NV, 384, HH);
    gemm_k<1><<<grd(NV, HH), 256>>>(nh0, nW1, nb1, nh1, NUL, NV, HH, HH);
    gemm_k<3><<<grd(NV, DD), 256>>>(nh1, nW2, nb2, vnew, out + (size_t)NE * DD, node_feat,
                                    nullptr, nullptr, nullptr, nullptr, nullptr, nullptr,
                                    NV, HH, DD);

    // graph readout of v_new
    node_seg_k<<<256, 256>>>(n2g);

    // attr MLP
    attrcat_k<<<4, 256>>>();
    gemm_k<1><<<grd(NG, HH), 256>>>(acat, aW0, ab0, ah0, NUL, NG, 384, HH);
    gemm_k<1><<<grd(NG, HH), 256>>>(ah0, aW1, ab1, ah1, NUL, NG, HH, HH);
    gemm_k<3><<<grd(NG, DD), 256>>>(ah1, aW2, ab2, unew,
                                    out + (size_t)NE * DD + (size_t)NV * DD, graph_attr,
                                    nullptr, nullptr, nullptr, nullptr, nullptr, nullptr,
                                    NG, HH, DD);
#undef NUL
}

// round 8
// speedup vs baseline: 1.7745x; 1.7583x over previous
#include <cuda_runtime.h>
#include <cstdint>
#include <math.h>

// Problem constants
#define NE 300000
#define NV 20000
#define NG 32
#define DD 128
#define HH 256

// GEMM tiling
#define KC 32            // K chunk
#define SROW 36          // padded smem row stride (floats): banks 4m+k, conflict-free
#define STAGE_F 9216     // floats per stage: A 128*36 + B 128*36
#define SMEM_BYTES (2 * STAGE_F * 4)   // 73728

// ---------------- scratch (device globals; no allocation allowed) ----------
__device__ float g_e_pre[NE * DD];
__device__ float g_v_pre[NV * DD];
__device__ float g_u_pre[NG * DD];
__device__ float g_vA[NV * HH];
__device__ float g_vB[NV * HH];
__device__ float g_uD[NG * HH];
__device__ float g_h0[NE * HH];
__device__ float g_h1[NE * HH];
__device__ float g_enew[NE * DD];
__device__ float g_vesum[NV * DD];
__device__ int   g_vcnt[NV];
__device__ float g_uesum[NG * DD];
__device__ int   g_ecnt[NG];
__device__ float g_uvsum[NG * DD];
__device__ int   g_ncnt[NG];
__device__ float g_ncat[NV * 3 * DD];
__device__ float g_nh0[NV * HH];
__device__ float g_nh1[NV * HH];
__device__ float g_vnew[NV * DD];
__device__ float g_acat[NG * 3 * DD];
__device__ float g_ah0[NG * HH];
__device__ float g_ah1[NG * HH];
__device__ float g_unew[NG * DD];
__device__ float g_wt[671744];   // weights transposed to [N,K], tf32-rounded

// ---------------- helpers ---------------------------------------------------
__device__ __forceinline__ uint32_t smem_u32(const void* p) {
    uint32_t a;
    asm("{ .reg .u64 t; cvta.to.shared.u64 t, %1; cvt.u32.u64 %0, t; }"
        : "=r"(a) : "l"(p));
    return a;
}
#define CP_ASYNC16(dst, src) \
    asm volatile("cp.async.cg.shared.global [%0], [%1], 16;" :: "r"(dst), "l"(src))
#define CP_COMMIT() asm volatile("cp.async.commit_group;" ::: "memory")
#define CP_WAIT(n)  asm volatile("cp.async.wait_group %0;" :: "n"(n) : "memory")

#define MMA_TF32(c, a, b0, b1) \
    asm volatile("mma.sync.aligned.m16n8k8.row.col.f32.tf32.tf32.f32 " \
        "{%0,%1,%2,%3}, {%4,%5,%6,%7}, {%8,%9}, {%0,%1,%2,%3};" \
        : "+f"((c)[0]), "+f"((c)[1]), "+f"((c)[2]), "+f"((c)[3]) \
        : "r"((a)[0]), "r"((a)[1]), "r"((a)[2]), "r"((a)[3]), "r"(b0), "r"(b1))

__device__ __forceinline__ float sp(float x) {
    // jax.nn.softplus = max(x,0) + log1p(exp(-|x|))
    return fmaxf(x, 0.f) + log1pf(__expf(-fabsf(x)));
}
__device__ __forceinline__ float rnd_tf32(float x) {
    uint32_t u;
    asm("cvt.rna.tf32.f32 %0, %1;" : "=r"(u) : "f"(x));
    return __uint_as_float(u);
}

// ---------------------------------------------------------------------------
// tf32 mma.sync GEMM: C[M,N] = epilogue(X[M,K] @ Wt^T), Wt is [N,K] row-major.
// MODE 0: C = X@W (+bias if non-null)                         (no round)
// MODE 1: C = rnd_tf32(softplus(X@W + bias))                  (GEMM input)
// MODE 2: C = rnd_tf32(softplus(X@W + gb1[i1]+gb2[i2]+gb3[n2g[i1]]))
// MODE 3: C = softplus(X@W + bias); out2 = C + skip           (final+residual)
// CTA 128x128, 8 warps (4m x 2n), warp tile 32x64, K chunks of 32,
// cp.async double-buffered. Requires K%32==0, N%128==0, lda==K.
// ---------------------------------------------------------------------------
template <int MODE>
__global__ void __launch_bounds__(256, 2)
tgemm(const float* __restrict__ X, int lda,
      const float* __restrict__ Wt, int ldw,
      const float* __restrict__ bias, float* __restrict__ C,
      float* __restrict__ out2, const float* __restrict__ skip,
      const float* __restrict__ gb1, const float* __restrict__ gb2,
      const float* __restrict__ gb3,
      const int* __restrict__ i1, const int* __restrict__ i2,
      const int* __restrict__ n2g,
      int M, int K, int N)
{
    extern __shared__ float smf[];
    const uint32_t sm0 = smem_u32(smf);

    const int tid = threadIdx.x;
    const int wid = tid >> 5, lid = tid & 31;
    const int gid = lid >> 2, tig = lid & 3;
    const int row0 = blockIdx.y * 128;
    const int col0 = blockIdx.x * 128;
    const int mbase = (wid >> 1) * 32;
    const int nbase = (wid & 1) * 64;

    // staging: thread covers row tid>>1, float4 cols (tid&1)+2j, j=0..3
    const int arow = tid >> 1;
    const int cq0  = tid & 1;
    const float* gA = X  + (size_t)min(row0 + arow, M - 1) * lda;
    const float* gB = Wt + (size_t)(col0 + arow) * ldw;
    const uint32_t sA = sm0 + (uint32_t)(arow * SROW) * 4;
    const uint32_t sB = sA + 4608u * 4;

    float acc[2][8][4];
#pragma unroll
    for (int mt = 0; mt < 2; mt++)
#pragma unroll
        for (int nt = 0; nt < 8; nt++)
#pragma unroll
            for (int q = 0; q < 4; q++) acc[mt][nt][q] = 0.f;

    const int nch = K / KC;

    // prefetch chunk 0 -> stage 0
#pragma unroll
    for (int j = 0; j < 4; j++) {
        const int c4 = cq0 + 2 * j;
        CP_ASYNC16(sA + (uint32_t)(c4 * 16), gA + c4 * 4);
        CP_ASYNC16(sB + (uint32_t)(c4 * 16), gB + c4 * 4);
    }
    CP_COMMIT();

    for (int c = 0; c < nch; c++) {
        if (c + 1 < nch) {
            const int k0 = (c + 1) * KC;
            const uint32_t soff = (uint32_t)(((c + 1) & 1) * STAGE_F) * 4;
#pragma unroll
            for (int j = 0; j < 4; j++) {
                const int c4 = cq0 + 2 * j;
                CP_ASYNC16(sA + soff + (uint32_t)(c4 * 16), gA + k0 + c4 * 4);
                CP_ASYNC16(sB + soff + (uint32_t)(c4 * 16), gB + k0 + c4 * 4);
            }
            CP_COMMIT();
            CP_WAIT(1);
        } else {
            CP_WAIT(0);
        }
        __syncthreads();

        const float* As = smf + (c & 1) * STAGE_F;
        const float* Bs = As + 4608;
#pragma unroll
        for (int ks = 0; ks < 4; ks++) {
            const int kf = ks * 8 + tig;
            uint32_t a[2][4];
#pragma unroll
            for (int mt = 0; mt < 2; mt++) {
                const float* ap = As + (mbase + mt * 16 + gid) * SROW + kf;
                a[mt][0] = __float_as_uint(ap[0]);
                a[mt][1] = __float_as_uint(ap[8 * SROW]);
                a[mt][2] = __float_as_uint(ap[4]);
                a[mt][3] = __float_as_uint(ap[8 * SROW + 4]);
            }
#pragma unroll
            for (int nt = 0; nt < 8; nt++) {
                const float* bp = Bs + (nbase + nt * 8 + gid) * SROW + kf;
                const uint32_t b0 = __float_as_uint(bp[0]);
                const uint32_t b1 = __float_as_uint(bp[4]);
                MMA_TF32(acc[0][nt], a[0], b0, b1);
                MMA_TF32(acc[1][nt], a[1], b0, b1);
            }
        }
        __syncthreads();
    }

    // ---------------- epilogue ----------------
    // c0,c1: row gid,   cols 2tig, 2tig+1
    // c2,c3: row gid+8, same cols
    float2 bv[8];
    if (bias) {
#pragma unroll
        for (int nt = 0; nt < 8; nt++)
            bv[nt] = *(const float2*)(bias + col0 + nbase + nt * 8 + tig * 2);
    } else {
#pragma unroll
        for (int nt = 0; nt < 8; nt++) bv[nt] = make_float2(0.f, 0.f);
    }

#pragma unroll
    for (int mt = 0; mt < 2; mt++) {
#pragma unroll
        for (int h = 0; h < 2; h++) {
            const int row = row0 + mbase + mt * 16 + gid + h * 8;
            if (row >= M) continue;
            const float *p1 = nullptr, *p2 = nullptr, *p3 = nullptr;
            if (MODE == 2) {
                const int s = i1[row], d = i2[row], g = n2g[s];
                p1 = gb1 + (size_t)s * N;
                p2 = gb2 + (size_t)d * N;
                p3 = gb3 + (size_t)g * N;
            }
            float* crow = C + (size_t)row * N;
#pragma unroll
            for (int nt = 0; nt < 8; nt++) {
                const int col = col0 + nbase + nt * 8 + tig * 2;
                float v0 = acc[mt][nt][h * 2 + 0] + bv[nt].x;
                float v1 = acc[mt][nt][h * 2 + 1] + bv[nt].y;
                if (MODE == 2) {
                    float2 a1 = *(const float2*)(p1 + col);
                    float2 a2 = *(const float2*)(p2 + col);
                    float2 a3 = *(const float2*)(p3 + col);
                    v0 += a1.x + a2.x + a3.x;
                    v1 += a1.y + a2.y + a3.y;
                }
                if (MODE != 0) { v0 = sp(v0); v1 = sp(v1); }
                if (MODE == 1 || MODE == 2) { v0 = rnd_tf32(v0); v1 = rnd_tf32(v1); }
                *(float2*)(crow + col) = make_float2(v0, v1);
                if (MODE == 3) {
                    float2 s2 = *(const float2*)(skip + (size_t)row * N + col);
                    *(float2*)(out2 + (size_t)row * N + col) =
                        make_float2(v0 + s2.x, v1 + s2.y);
                }
            }
        }
    }
}

// ---------------- weight transpose + tf32 round ----------------------------
__global__ void wt_k(const float* __restrict__ W, float* __restrict__ Wt, int K, int N)
{
    int idx = blockIdx.x * blockDim.x + threadIdx.x;
    if (idx >= K * N) return;
    int k = idx / N, n = idx - k * N;
    Wt[(size_t)n * K + k] = rnd_tf32(W[idx]);
}

// ---------------- segment-count kernel -------------------------------------
__global__ void counts_k(const int* __restrict__ src, const int* __restrict__ dst,
                         const int* __restrict__ n2g)
{
    int i = blockIdx.x * blockDim.x + threadIdx.x;
    if (i < NE) {
        atomicAdd(&g_vcnt[dst[i]], 1);
        atomicAdd(&g_ecnt[n2g[src[i]]], 1);
    }
    if (i < NV) atomicAdd(&g_ncnt[n2g[i]], 1);
}

// ---------------- edge segment sums: ve_sum (by dst), ue_sum (by graph) ----
__global__ void edge_seg_k(const int* __restrict__ src, const int* __restrict__ dst,
                           const int* __restrict__ n2g)
{
    __shared__ float s_ue[NG * DD];
    for (int i = threadIdx.x; i < NG * DD; i += blockDim.x) s_ue[i] = 0.f;
    __syncthreads();

    const int total = NE * (DD / 4);
    for (int idx = blockIdx.x * blockDim.x + threadIdx.x; idx < total;
         idx += gridDim.x * blockDim.x) {
        int e = idx >> 5;
        int c = (idx & 31) * 4;
        float4 v = *(const float4*)(g_enew + (size_t)e * DD + c);
        int dn = dst[e];
        int g  = n2g[src[e]];
        float* vp = g_vesum + (size_t)dn * DD + c;
        atomicAdd(vp + 0, v.x); atomicAdd(vp + 1, v.y);
        atomicAdd(vp + 2, v.z); atomicAdd(vp + 3, v.w);
        float* up = s_ue + g * DD + c;
        atomicAdd(up + 0, v.x); atomicAdd(up + 1, v.y);
        atomicAdd(up + 2, v.z); atomicAdd(up + 3, v.w);
    }
    __syncthreads();
    for (int i = threadIdx.x; i < NG * DD; i += blockDim.x) {
        float v = s_ue[i];
        if (v != 0.f) atomicAdd(&g_uesum[i], v);
    }
}

// ---------------- node segment sums: uv_sum (by graph) ---------------------
__global__ void node_seg_k(const int* __restrict__ n2g)
{
    __shared__ float s_uv[NG * DD];
    for (int i = threadIdx.x; i < NG * DD; i += blockDim.x) s_uv[i] = 0.f;
    __syncthreads();

    const int total = NV * (DD / 4);
    for (int idx = blockIdx.x * blockDim.x + threadIdx.x; idx < total;
         idx += gridDim.x * blockDim.x) {
        int node = idx >> 5;
        int c = (idx & 31) * 4;
        float4 v = *(const float4*)(g_vnew + (size_t)node * DD + c);
        int g = n2g[node];
        float* up = s_uv + g * DD + c;
        atomicAdd(up + 0, v.x); atomicAdd(up + 1, v.y);
        atomicAdd(up + 2, v.z); atomicAdd(up + 3, v.w);
    }
    __syncthreads();
    for (int i = threadIdx.x; i < NG * DD; i += blockDim.x) {
        float v = s_uv[i];
        if (v != 0.f) atomicAdd(&g_uvsum[i], v);
    }
}

// ---------------- node concat: [v_pre | rnd(ve_mean) | u_pre[g]] -----------
__global__ void nodecat_k(const int* __restrict__ n2g)
{
    int idx = blockIdx.x * blockDim.x + threadIdx.x;
    const int total = NV * (DD / 4);
    if (idx >= total) return;
    int node = idx >> 5;
    int c = (idx & 31) * 4;

    float4 vp = *(const float4*)(g_v_pre + (size_t)node * DD + c);
    *(float4*)(g_ncat + (size_t)node * 384 + c) = vp;

    float cnt = fmaxf((float)g_vcnt[node], 1.f);
    float4 ve = *(const float4*)(g_vesum + (size_t)node * DD + c);
    ve.x = rnd_tf32(ve.x / cnt); ve.y = rnd_tf32(ve.y / cnt);
    ve.z = rnd_tf32(ve.z / cnt); ve.w = rnd_tf32(ve.w / cnt);
    *(float4*)(g_ncat + (size_t)node * 384 + 128 + c) = ve;

    int g = n2g[node];
    float4 up = *(const float4*)(g_u_pre + (size_t)g * DD + c);
    *(float4*)(g_ncat + (size_t)node * 384 + 256 + c) = up;
}

// ---------------- attr concat: [u_pre | rnd(ue_mean) | rnd(uv_mean)] -------
__global__ void attrcat_k()
{
    int idx = blockIdx.x * blockDim.x + threadIdx.x;
    if (idx >= NG * (DD / 4)) return;
    int g = idx >> 5;
    int c = (idx & 31) * 4;

    float4 u = *(const float4*)(g_u_pre + (size_t)g * DD + c);
    *(float4*)(g_acat + (size_t)g * 384 + c) = u;

    float ec = fmaxf((float)g_ecnt[g], 1.f);
    float4 ue = *(const float4*)(g_uesum + (size_t)g * DD + c);
    ue.x = rnd_tf32(ue.x / ec); ue.y = rnd_tf32(ue.y / ec);
    ue.z = rnd_tf32(ue.z / ec); ue.w = rnd_tf32(ue.w / ec);
    *(float4*)(g_acat + (size_t)g * 384 + 128 + c) = ue;

    float nc = fmaxf((float)g_ncnt[g], 1.f);
    float4 uv = *(const float4*)(g_uvsum + (size_t)g * DD + c);
    uv.x = rnd_tf32(uv.x / nc); uv.y = rnd_tf32(uv.y / nc);
    uv.z = rnd_tf32(uv.z / nc); uv.w = rnd_tf32(uv.w / nc);
    *(float4*)(g_acat + (size_t)g * 384 + 256 + c) = uv;
}

// ---------------------------------------------------------------------------
extern "C" void kernel_launch(void* const* d_in, const int* in_sizes, int n_in,
                              void* d_out, int out_size)
{
    const float* edge_feat  = (const float*)d_in[0];
    const float* node_feat  = (const float*)d_in[1];
    const float* graph_attr = (const float*)d_in[2];
    const int*   src        = (const int*)d_in[3];
    const int*   dst        = (const int*)d_in[4];
    const int*   n2g        = (const int*)d_in[5];
    const float* peW = (const float*)d_in[6],  *peb = (const float*)d_in[7];
    const float* pnW = (const float*)d_in[8],  *pnb = (const float*)d_in[9];
    const float* paW = (const float*)d_in[10], *pab = (const float*)d_in[11];
    const float* eW0 = (const float*)d_in[12], *eb0 = (const float*)d_in[13];
    const float* eW1 = (const float*)d_in[14], *eb1 = (const float*)d_in[15];
    const float* eW2 = (const float*)d_in[16], *eb2 = (const float*)d_in[17];
    const float* nW0 = (const float*)d_in[18], *nb0 = (const float*)d_in[19];
    const float* nW1 = (const float*)d_in[20], *nb1 = (const float*)d_in[21];
    const float* nW2 = (const float*)d_in[22], *nb2 = (const float*)d_in[23];
    const float* aW0 = (const float*)d_in[24], *ab0 = (const float*)d_in[25];
    const float* aW1 = (const float*)d_in[26], *ab1 = (const float*)d_in[27];
    const float* aW2 = (const float*)d_in[28], *ab2 = (const float*)d_in[29];
    float* out = (float*)d_out;

    float *e_pre, *v_pre, *u_pre, *vA, *vB, *uD, *h0, *h1, *enew;
    float *vesum, *uesum, *uvsum, *ncat, *nh0, *nh1, *vnew, *acat, *ah0, *ah1, *unew, *wt;
    int *vcnt, *ecnt, *ncnt;
    cudaGetSymbolAddress((void**)&e_pre, g_e_pre);
    cudaGetSymbolAddress((void**)&v_pre, g_v_pre);
    cudaGetSymbolAddress((void**)&u_pre, g_u_pre);
    cudaGetSymbolAddress((void**)&vA,    g_vA);
    cudaGetSymbolAddress((void**)&vB,    g_vB);
    cudaGetSymbolAddress((void**)&uD,    g_uD);
    cudaGetSymbolAddress((void**)&h0,    g_h0);
    cudaGetSymbolAddress((void**)&h1,    g_h1);
    cudaGetSymbolAddress((void**)&enew,  g_enew);
    cudaGetSymbolAddress((void**)&vesum, g_vesum);
    cudaGetSymbolAddress((void**)&uesum, g_uesum);
    cudaGetSymbolAddress((void**)&uvsum, g_uvsum);
    cudaGetSymbolAddress((void**)&ncat,  g_ncat);
    cudaGetSymbolAddress((void**)&nh0,   g_nh0);
    cudaGetSymbolAddress((void**)&nh1,   g_nh1);
    cudaGetSymbolAddress((void**)&vnew,  g_vnew);
    cudaGetSymbolAddress((void**)&acat,  g_acat);
    cudaGetSymbolAddress((void**)&ah0,   g_ah0);
    cudaGetSymbolAddress((void**)&ah1,   g_ah1);
    cudaGetSymbolAddress((void**)&unew,  g_unew);
    cudaGetSymbolAddress((void**)&wt,    g_wt);
    cudaGetSymbolAddress((void**)&vcnt,  g_vcnt);
    cudaGetSymbolAddress((void**)&ecnt,  g_ecnt);
    cudaGetSymbolAddress((void**)&ncnt,  g_ncnt);

    // transposed-weight offsets (floats)
    float* peWt = wt + 0;
    float* pnWt = wt + 16384;
    float* paWt = wt + 32768;
    float* eW0t = wt + 49152;    // [256, 512]
    float* eW1t = wt + 180224;   // [256, 256]
    float* eW2t = wt + 245760;   // [128, 256]
    float* nW0t = wt + 278528;   // [256, 384]
    float* nW1t = wt + 376832;   // [256, 256]
    float* nW2t = wt + 442368;   // [128, 256]
    float* aW0t = wt + 475136;   // [256, 384]
    float* aW1t = wt + 573440;   // [256, 256]
    float* aW2t = wt + 638976;   // [128, 256]

    cudaFuncSetAttribute(tgemm<0>, cudaFuncAttributeMaxDynamicSharedMemorySize, SMEM_BYTES);
    cudaFuncSetAttribute(tgemm<1>, cudaFuncAttributeMaxDynamicSharedMemorySize, SMEM_BYTES);
    cudaFuncSetAttribute(tgemm<2>, cudaFuncAttributeMaxDynamicSharedMemorySize, SMEM_BYTES);
    cudaFuncSetAttribute(tgemm<3>, cudaFuncAttributeMaxDynamicSharedMemorySize, SMEM_BYTES);

    // zero the accumulators (graph-capturable memset nodes)
    cudaMemsetAsync(vesum, 0, sizeof(float) * NV * DD, 0);
    cudaMemsetAsync(vcnt,  0, sizeof(int) * NV, 0);
    cudaMemsetAsync(uesum, 0, sizeof(float) * NG * DD, 0);
    cudaMemsetAsync(ecnt,  0, sizeof(int) * NG, 0);
    cudaMemsetAsync(uvsum, 0, sizeof(float) * NG * DD, 0);
    cudaMemsetAsync(ncnt,  0, sizeof(int) * NG, 0);

    // transpose + tf32-round all weights
    auto wtl = [](const float* Wsrc, float* Wdst, int K, int N) {
        wt_k<<<(K * N + 255) / 256, 256>>>(Wsrc, Wdst, K, N);
    };
    wtl(peW, peWt, 128, 128);
    wtl(pnW, pnWt, 128, 128);
    wtl(paW, paWt, 128, 128);
    wtl(eW0, eW0t, 512, 256);
    wtl(eW1, eW1t, 256, 256);
    wtl(eW2, eW2t, 256, 128);
    wtl(nW0, nW0t, 384, 256);
    wtl(nW1, nW1t, 256, 256);
    wtl(nW2, nW2t, 256, 128);
    wtl(aW0, aW0t, 384, 256);
    wtl(aW1, aW1t, 256, 256);
    wtl(aW2, aW2t, 256, 128);

    auto grd = [](int M, int N) {
        return dim3((unsigned)(N / 128), (unsigned)((M + 127) / 128));
    };
#define NUL6 nullptr, nullptr, nullptr, nullptr, nullptr, nullptr
#define NUL8 nullptr, nullptr, NUL6

    // pre-dense MLPs (outputs tf32-rounded: GEMM inputs)
    tgemm<1><<<grd(NE, 128), 256, SMEM_BYTES>>>(edge_feat, 128, peWt, 128, peb, e_pre,
                                                NUL8, NE, 128, 128);
    tgemm<1><<<grd(NV, 128), 256, SMEM_BYTES>>>(node_feat, 128, pnWt, 128, pnb, v_pre,
                                                NUL8, NV, 128, 128);
    tgemm<1><<<grd(NG, 128), 256, SMEM_BYTES>>>(graph_attr, 128, paWt, 128, pab, u_pre,
                                                NUL8, NG, 128, 128);

    // per-node / per-graph partial products of edge layer 0 (K-panel split; fp32 out)
    tgemm<0><<<grd(NV, 256), 256, SMEM_BYTES>>>(v_pre, 128, eW0t + 0,   512, nullptr, vA,
                                                NUL8, NV, 128, 256);
    tgemm<0><<<grd(NV, 256), 256, SMEM_BYTES>>>(v_pre, 128, eW0t + 128, 512, nullptr, vB,
                                                NUL8, NV, 128, 256);
    tgemm<0><<<grd(NG, 256), 256, SMEM_BYTES>>>(u_pre, 128, eW0t + 384, 512, eb0, uD,
                                                NUL8, NG, 128, 256);

    counts_k<<<(NE + 255) / 256, 256>>>(src, dst, n2g);

    // edge MLP
    tgemm<2><<<grd(NE, 256), 256, SMEM_BYTES>>>(e_pre, 128, eW0t + 256, 512, nullptr, h0,
                                                nullptr, nullptr, vA, vB, uD,
                                                src, dst, n2g, NE, 128, 256);
    tgemm<1><<<grd(NE, 256), 256, SMEM_BYTES>>>(h0, 256, eW1t, 256, eb1, h1,
                                                NUL8, NE, 256, 256);
    tgemm<3><<<grd(NE, 128), 256, SMEM_BYTES>>>(h1, 256, eW2t, 256, eb2, enew,
                                                out, edge_feat, NUL6, NE, 256, 128);

    // segment means of e_new
    edge_seg_k<<<512, 256>>>(src, dst, n2g);

    // node MLP
    nodecat_k<<<(NV * 32 + 255) / 256, 256>>>(n2g);
    tgemm<1><<<grd(NV, 256), 256, SMEM_BYTES>>>(ncat, 384, nW0t, 384, nb0, nh0,
                                                NUL8, NV, 384, 256);
    tgemm<1><<<grd(NV, 256), 256, SMEM_BYTES>>>(nh0, 256, nW1t, 256, nb1, nh1,
                                                NUL8, NV, 256, 256);
    tgemm<3><<<grd(NV, 128), 256, SMEM_BYTES>>>(nh1, 256, nW2t, 256, nb2, vnew,
                                                out + (size_t)NE * DD, node_feat,
                                                NUL6, NV, 256, 128);

    // graph readout of v_new
    node_seg_k<<<256, 256>>>(n2g);

    // attr MLP
    attrcat_k<<<4, 256>>>();
    tgemm<1><<<grd(NG, 256), 256, SMEM_BYTES>>>(acat, 384, aW0t, 384, ab0, ah0,
                                                NUL8, NG, 384, 256);
    tgemm<1><<<grd(NG, 256), 256, SMEM_BYTES>>>(ah0, 256, aW1t, 256, ab1, ah1,
                                                NUL8, NG, 256, 256);
    tgemm<3><<<grd(NG, 128), 256, SMEM_BYTES>>>(ah1, 256, aW2t, 256, ab2, unew,
                                                out + (size_t)NE * DD + (size_t)NV * DD,
                                                graph_attr, NUL6, NG, 256, 128);
#undef NUL6
#undef NUL8
}